// round 16
// baseline (speedup 1.0000x reference)
#include <cuda_runtime.h>
#include <cuda_fp16.h>
#include <cstdint>

#define DIM     768
#define NHEADS  12
#define HDIM    64
#define BATCH   8
#define SEQ     1024
#define MTOT    (BATCH * SEQ)      // 8192
#define QKVN    (3 * DIM)          // 2304
// Q pre-scale: 1/sqrt(64) * log2(e)  (softmax done in exp2 domain, no shift)
#define QK_SCALE (0.125f * 1.4426950408889634f)

// ---------------------------------------------------------------------------
// Scratch (__device__ globals; no allocations allowed)
// ---------------------------------------------------------------------------
__device__ __half g_qh[BATCH * NHEADS * SEQ * HDIM];
__device__ __half g_kh[BATCH * NHEADS * SEQ * HDIM];
__device__ __half g_vh[BATCH * NHEADS * HDIM * SEQ];     // [B,H,D,N]
__device__ __half g_xh[MTOT * DIM];
__device__ __half g_wqh[QKVN * DIM];
__device__ __half g_wph[DIM * DIM];
__device__ __half g_ah[MTOT * DIM];

__device__ __forceinline__ uint32_t smem_u32(const void* p) {
    uint32_t a;
    asm("{ .reg .u64 t; cvta.to.shared.u64 t, %1; cvt.u32.u64 %0, t; }"
        : "=r"(a) : "l"(p));
    return a;
}

#define SWZ(off) ((off) ^ (((off) >> 3) & 0x70))

#define LDSM_X4(r0, r1, r2, r3, addr) \
    asm volatile("ldmatrix.sync.aligned.m8n8.x4.shared.b16 {%0,%1,%2,%3}, [%4];" \
        : "=r"(r0), "=r"(r1), "=r"(r2), "=r"(r3) : "r"(addr))

#define MBAR_INIT(addr, cnt) \
    asm volatile("mbarrier.init.shared.b64 [%0], %1;" \
        :: "r"((uint32_t)(addr)), "r"((uint32_t)(cnt)) : "memory")
#define MBAR_ARRIVE(addr) \
    asm volatile("mbarrier.arrive.shared.b64 _, [%0];" \
        :: "r"((uint32_t)(addr)) : "memory")
#define MBAR_WAIT(mbar_smem_addr, phase_parity) do { \
    uint32_t _mbar = (uint32_t)(mbar_smem_addr); \
    uint32_t _parity = (uint32_t)(phase_parity); \
    uint32_t _done; \
    asm volatile("{\n\t.reg .pred p;\n\t" \
        "mbarrier.try_wait.parity.acquire.cta.shared::cta.b64 p, [%1], %2;\n\t" \
        "selp.b32 %0, 1, 0, p;\n\t}" \
        : "=r"(_done) : "r"(_mbar), "r"(_parity) : "memory"); \
    if (!_done) { \
        asm volatile("{\n\t.reg .pred P1;\n\t" \
            "WAIT_LOOP_%=:\n\t" \
            "mbarrier.try_wait.parity.acquire.cta.shared::cta.b64 P1, [%0], %1, 0x989680;\n\t" \
            "@P1 bra.uni WAIT_DONE_%=;\n\t" \
            "bra.uni WAIT_LOOP_%=;\n\t" \
            "WAIT_DONE_%=:\n\t}" \
            :: "r"(_mbar), "r"(_parity) : "memory"); \
    } \
} while (0)

__device__ __forceinline__ void mma16816(float* c, const uint32_t* a,
                                         const uint32_t* b)
{
    asm volatile("mma.sync.aligned.m16n8k16.row.col.f32.f16.f16.f32 "
        "{%0,%1,%2,%3}, {%4,%5,%6,%7}, {%8,%9}, {%0,%1,%2,%3};"
        : "+f"(c[0]), "+f"(c[1]), "+f"(c[2]), "+f"(c[3])
        : "r"(a[0]), "r"(a[1]), "r"(a[2]), "r"(a[3]), "r"(b[0]), "r"(b[1]));
}

__device__ __forceinline__ uint32_t packh2(__half x, __half y) {
    __half2 t = __half2(x, y);
    return *(uint32_t*)&t;
}
__device__ __forceinline__ float ex2(float x) {
    float y;
    asm("ex2.approx.ftz.f32 %0, %1;" : "=f"(y) : "f"(x));
    return y;
}

// ---------------------------------------------------------------------------
// Fused conversion: pure fp32 -> fp16 casts for x, w_qkv, w_proj
// ---------------------------------------------------------------------------
#define SPLIT_Q1 (MTOT * DIM / 4)
#define SPLIT_Q2 (SPLIT_Q1 + QKVN * DIM / 4)
#define SPLIT_Q3 (SPLIT_Q2 + DIM * DIM / 4)

__global__ __launch_bounds__(256)
void split_all_kernel(const float* __restrict__ x, const float* __restrict__ wq,
                      const float* __restrict__ wp)
{
    int i = blockIdx.x * blockDim.x + threadIdx.x;
    if (i >= SPLIT_Q3) return;

    const float* src;
    __half* dst;
    int off;
    if (i < SPLIT_Q1)      { src = x;  dst = g_xh;  off = i; }
    else if (i < SPLIT_Q2) { src = wq; dst = g_wqh; off = i - SPLIT_Q1; }
    else                   { src = wp; dst = g_wph; off = i - SPLIT_Q2; }

    float4 v = ((const float4*)src)[off];
    __half2* hp = (__half2*)(dst + off * 4);
    hp[0] = __half2(__float2half(v.x), __float2half(v.y));
    hp[1] = __half2(__float2half(v.z), __float2half(v.w));
}

// ---------------------------------------------------------------------------
// Plain-fp16 HMMA GEMM core config: CTA 128x128, 8 warps (2m x 4n),
// warp tile 64x32, KC=64, 2-stage cp.async, 64KB smem -> 2 CTAs/SM.
// ---------------------------------------------------------------------------
#define KC        64
#define NKC       (DIM / KC)                 // 12
#define G_AH      0
#define G_BH      16384
#define G_STAGE   32768
#define G_MBAR    (2 * G_STAGE)
#define GEMM_SMEM (2 * G_STAGE + 64)

__device__ __forceinline__ void cp_tile128(uint32_t dst, const __half* g, int tid)
{
#pragma unroll
    for (int i = 0; i < 4; i++) {
        const int p = tid + i * 256;
        const int r = p >> 3;
        const int c = p & 7;
        const uint32_t off = (uint32_t)(r * 128 + c * 16);
        const void* src = (const char*)(g + (size_t)r * DIM) + c * 16;
        asm volatile("cp.async.cg.shared.global [%0], [%1], 16;"
                     :: "r"(dst + SWZ(off)), "l"(src) : "memory");
    }
}

// ---- QKV GEMM: scatter q/k/v fp16 (Q pre-scaled, V transposed direct) ----
__global__ __launch_bounds__(256, 2)
void qkv_gemm_kernel(const __half* __restrict__ Ah, const __half* __restrict__ Bh)
{
    extern __shared__ char smem[];
    const uint32_t sbase = smem_u32(smem);
    const int tid  = threadIdx.x;
    const int wid  = tid >> 5;
    const int lane = tid & 31;
    const int wm   = wid >> 2;
    const int wn   = wid & 3;
    const int n0   = blockIdx.x * 128;
    const int m0   = blockIdx.y * 128;

    if (tid == 0) {
        MBAR_INIT(sbase + G_MBAR, 256);
        MBAR_INIT(sbase + G_MBAR + 8, 256);
    }

    const __half* Ah0 = Ah + (size_t)m0 * DIM;
    const __half* Bh0 = Bh + (size_t)n0 * DIM;

    float acc[4][4][4];
#pragma unroll
    for (int i = 0; i < 4; i++)
#pragma unroll
        for (int j = 0; j < 4; j++)
#pragma unroll
            for (int k = 0; k < 4; k++) acc[i][j][k] = 0.f;

    {
        cp_tile128(sbase + G_AH, Ah0, tid);
        cp_tile128(sbase + G_BH, Bh0, tid);
        asm volatile("cp.async.commit_group;" ::: "memory");
    }

    const int a_row = wm * 64 + (lane & 15);
    const int a_kh  = (lane >> 4) * 16;
    const int b_row = wn * 32 + (lane & 7) + ((lane >> 4) << 3);
    const int b_kh  = ((lane >> 3) & 1) * 16;

    int ph[2] = {0, 0};

    for (int kc = 0; kc < NKC; kc++) {
        if (kc + 1 < NKC) {
            const int t = (kc + 1) & 1;
            if (kc >= 1) {
                MBAR_WAIT(sbase + G_MBAR + t * 8, ph[t]);
                ph[t] ^= 1;
            }
            const uint32_t st = sbase + t * G_STAGE;
            const int koff = (kc + 1) * KC;
            cp_tile128(st + G_AH, Ah0 + koff, tid);
            cp_tile128(st + G_BH, Bh0 + koff, tid);
            asm volatile("cp.async.commit_group;" ::: "memory");
            asm volatile("cp.async.wait_group 1;" ::: "memory");
        } else {
            asm volatile("cp.async.wait_group 0;" ::: "memory");
        }
        __syncthreads();

        const uint32_t st = sbase + (kc & 1) * G_STAGE;
        const uint32_t sAh = st + G_AH;
        const uint32_t sBh = st + G_BH;

#pragma unroll
        for (int ks = 0; ks < KC / 16; ks++) {
            uint32_t ah[4][4], bh[2][4];
#pragma unroll
            for (int mf = 0; mf < 4; mf++) {
                uint32_t off = (uint32_t)((a_row + mf * 16) * 128 + ks * 32 + a_kh);
                LDSM_X4(ah[mf][0], ah[mf][1], ah[mf][2], ah[mf][3], sAh + SWZ(off));
            }
#pragma unroll
            for (int nfp = 0; nfp < 2; nfp++) {
                uint32_t off = (uint32_t)((b_row + nfp * 16) * 128 + ks * 32 + b_kh);
                LDSM_X4(bh[nfp][0], bh[nfp][1], bh[nfp][2], bh[nfp][3], sBh + SWZ(off));
            }
            if (ks == KC / 16 - 1)
                MBAR_ARRIVE(sbase + G_MBAR + (kc & 1) * 8);
#pragma unroll
            for (int mf = 0; mf < 4; mf++)
#pragma unroll
                for (int nf = 0; nf < 4; nf++)
                    mma16816(acc[mf][nf], ah[mf], &bh[nf >> 1][(nf & 1) * 2]);
        }
    }

    const int rbase = m0 + wm * 64 + (lane >> 2);
    const int cbase = n0 + wn * 32 + (lane & 3) * 2;
    const int sel = n0 / DIM;

#pragma unroll
    for (int nf = 0; nf < 4; nf++) {
        const int gc = cbase + nf * 8;
        const int h  = (gc % DIM) >> 6;
        const int d  = gc & 63;
#pragma unroll
        for (int mf = 0; mf < 4; mf++) {
#pragma unroll
            for (int rr = 0; rr < 2; rr++) {
                const int m = rbase + mf * 16 + rr * 8;
                const int b = m >> 10;
                const int n = m & 1023;
                float v0 = acc[mf][nf][rr * 2];
                float v1 = acc[mf][nf][rr * 2 + 1];
                if (sel == 0) {
                    v0 *= QK_SCALE; v1 *= QK_SCALE;
                    const size_t a = ((size_t)((b * NHEADS + h) * SEQ + n)) * HDIM + d;
                    *(__half2*)(g_qh + a) = __half2(__float2half(v0), __float2half(v1));
                } else if (sel == 1) {
                    const size_t a = ((size_t)((b * NHEADS + h) * SEQ + n)) * HDIM + d;
                    *(__half2*)(g_kh + a) = __half2(__float2half(v0), __float2half(v1));
                } else {
                    const size_t a = ((size_t)((b * NHEADS + h) * HDIM + d)) * SEQ + n;
                    g_vh[a]       = __float2half(v0);
                    g_vh[a + SEQ] = __float2half(v1);
                }
            }
        }
    }
}

// ---------------------------------------------------------------------------
// Proj GEMM v2: CTA 128x96 (wave shaping: 512 CTAs / 592 slots = 86.5%),
// 8 warps (4m x 2n), warp tile 32x48, KC=64, 2-stage, 56KB smem, 2 CTAs/SM.
// OUT = Ah @ Wh^T + bias
// ---------------------------------------------------------------------------
#define P_AH      0                          // 128 x 64h = 16KB
#define P_BH      16384                      // 96 x 64h = 12KB
#define P_STAGE   28672
#define P_MBAR    (2 * P_STAGE)
#define PROJ_SMEM (2 * P_STAGE + 64)

__device__ __forceinline__ void cp_tile96(uint32_t dst, const __half* g, int tid)
{
#pragma unroll
    for (int i = 0; i < 3; i++) {
        const int p = tid + i * 256;
        const int r = p >> 3;
        const int c = p & 7;
        const uint32_t off = (uint32_t)(r * 128 + c * 16);
        const void* src = (const char*)(g + (size_t)r * DIM) + c * 16;
        asm volatile("cp.async.cg.shared.global [%0], [%1], 16;"
                     :: "r"(dst + SWZ(off)), "l"(src) : "memory");
    }
}

__global__ __launch_bounds__(256, 2)
void proj_gemm_kernel(const __half* __restrict__ Ah, const __half* __restrict__ Bh,
                      const float* __restrict__ bias, float* __restrict__ OUT)
{
    extern __shared__ char smem[];
    const uint32_t sbase = smem_u32(smem);
    const int tid  = threadIdx.x;
    const int wid  = tid >> 5;
    const int lane = tid & 31;
    const int wm   = wid >> 1;          // 0..3
    const int wn   = wid & 1;           // 0..1
    const int n0   = blockIdx.x * 96;
    const int m0   = blockIdx.y * 128;

    if (tid == 0) {
        MBAR_INIT(sbase + P_MBAR, 256);
        MBAR_INIT(sbase + P_MBAR + 8, 256);
    }

    const __half* Ah0 = Ah + (size_t)m0 * DIM;
    const __half* Bh0 = Bh + (size_t)n0 * DIM;

    float acc[2][6][4];
#pragma unroll
    for (int i = 0; i < 2; i++)
#pragma unroll
        for (int j = 0; j < 6; j++)
#pragma unroll
            for (int k = 0; k < 4; k++) acc[i][j][k] = 0.f;

    {
        cp_tile128(sbase + P_AH, Ah0, tid);
        cp_tile96 (sbase + P_BH, Bh0, tid);
        asm volatile("cp.async.commit_group;" ::: "memory");
    }

    const int a_row = wm * 32 + (lane & 15);
    const int a_kh  = (lane >> 4) * 16;
    const int b_row = wn * 48 + (lane & 7) + ((lane >> 4) << 3);
    const int b_kh  = ((lane >> 3) & 1) * 16;

    int ph[2] = {0, 0};

    for (int kc = 0; kc < NKC; kc++) {
        if (kc + 1 < NKC) {
            const int t = (kc + 1) & 1;
            if (kc >= 1) {
                MBAR_WAIT(sbase + P_MBAR + t * 8, ph[t]);
                ph[t] ^= 1;
            }
            const uint32_t st = sbase + t * P_STAGE;
            const int koff = (kc + 1) * KC;
            cp_tile128(st + P_AH, Ah0 + koff, tid);
            cp_tile96 (st + P_BH, Bh0 + koff, tid);
            asm volatile("cp.async.commit_group;" ::: "memory");
            asm volatile("cp.async.wait_group 1;" ::: "memory");
        } else {
            asm volatile("cp.async.wait_group 0;" ::: "memory");
        }
        __syncthreads();

        const uint32_t st = sbase + (kc & 1) * P_STAGE;
        const uint32_t sAh = st + P_AH;
        const uint32_t sBh = st + P_BH;

#pragma unroll
        for (int ks = 0; ks < KC / 16; ks++) {
            uint32_t ah[2][4], bh[3][4];
#pragma unroll
            for (int mf = 0; mf < 2; mf++) {
                uint32_t off = (uint32_t)((a_row + mf * 16) * 128 + ks * 32 + a_kh);
                LDSM_X4(ah[mf][0], ah[mf][1], ah[mf][2], ah[mf][3], sAh + SWZ(off));
            }
#pragma unroll
            for (int nfp = 0; nfp < 3; nfp++) {
                uint32_t off = (uint32_t)((b_row + nfp * 16) * 128 + ks * 32 + b_kh);
                LDSM_X4(bh[nfp][0], bh[nfp][1], bh[nfp][2], bh[nfp][3], sBh + SWZ(off));
            }
            if (ks == KC / 16 - 1)
                MBAR_ARRIVE(sbase + P_MBAR + (kc & 1) * 8);
#pragma unroll
            for (int mf = 0; mf < 2; mf++)
#pragma unroll
                for (int nf = 0; nf < 6; nf++)
                    mma16816(acc[mf][nf], ah[mf], &bh[nf >> 1][(nf & 1) * 2]);
        }
    }

    const int rbase = m0 + wm * 32 + (lane >> 2);
    const int cbase = n0 + wn * 48 + (lane & 3) * 2;

#pragma unroll
    for (int nf = 0; nf < 6; nf++) {
        const int gc = cbase + nf * 8;
        const float2 bv = *(const float2*)(bias + gc);
#pragma unroll
        for (int mf = 0; mf < 2; mf++) {
#pragma unroll
            for (int rr = 0; rr < 2; rr++) {
                const int m = rbase + mf * 16 + rr * 8;
                float* p = OUT + (size_t)m * DIM + gc;
                *(float2*)p = make_float2(acc[mf][nf][rr * 2] + bv.x,
                                          acc[mf][nf][rr * 2 + 1] + bv.y);
            }
        }
    }
}

// ---------------------------------------------------------------------------
// fp16 flash attention (measured best): q-tile 128, 2 CTAs/SM,
// static-shift softmax. KV j-tile 64, 2-stage cp.async; 48KB smem.
// ---------------------------------------------------------------------------
#define A_QH     0                 // 128 x 64h = 16KB
#define A_ST     16384             // stage: KH 0, VH 8192
#define A_STAGEB 16384
#define A_MBAR   (A_ST + 2 * A_STAGEB)
#define A_SMEM   (A_MBAR + 64)

__device__ __forceinline__ void cp_kv64(uint32_t dst, const __half* g, int tid)
{
#pragma unroll
    for (int i = 0; i < 2; i++) {
        const int p = tid + i * 256;
        const int r = p >> 3;
        const int c = p & 7;
        const uint32_t off = (uint32_t)(r * 128 + c * 16);
        const void* src = (const char*)(g + (size_t)r * 64) + c * 16;
        asm volatile("cp.async.cg.shared.global [%0], [%1], 16;"
                     :: "r"(dst + SWZ(off)), "l"(src) : "memory");
    }
}
__device__ __forceinline__ void cp_q128(uint32_t dst, const __half* g, int tid)
{
#pragma unroll
    for (int i = 0; i < 4; i++) {
        const int p = tid + i * 256;
        const int r = p >> 3;
        const int c = p & 7;
        const uint32_t off = (uint32_t)(r * 128 + c * 16);
        const void* src = (const char*)(g + (size_t)r * 64) + c * 16;
        asm volatile("cp.async.cg.shared.global [%0], [%1], 16;"
                     :: "r"(dst + SWZ(off)), "l"(src) : "memory");
    }
}
__device__ __forceinline__ void cp_v64(uint32_t dst, const __half* g, int j0, int tid)
{
#pragma unroll
    for (int i = 0; i < 2; i++) {
        const int p = tid + i * 256;
        const int d = p >> 3;
        const int c = p & 7;
        const void* src = g + (size_t)d * SEQ + j0 + c * 8;
        const uint32_t off = (uint32_t)(d * 128 + c * 16);
        asm volatile("cp.async.cg.shared.global [%0], [%1], 16;"
                     :: "r"(dst + SWZ(off)), "l"(src) : "memory");
    }
}

__global__ __launch_bounds__(256, 2)
void attn_hmma_kernel()
{
    extern __shared__ char smem[];
    const uint32_t sb = smem_u32(smem);
    const int tid = threadIdx.x, wid = tid >> 5, lane = tid & 31;
    const int bh = blockIdx.x, qt = blockIdx.y;

    if (tid == 0) {
        MBAR_INIT(sb + A_MBAR, 256);
        MBAR_INIT(sb + A_MBAR + 8, 256);
    }

    const __half* qhg = g_qh + ((size_t)bh * SEQ + qt * 128) * HDIM;
    const __half* khg = g_kh + (size_t)bh * SEQ * HDIM;
    const __half* vhg = g_vh + (size_t)bh * HDIM * SEQ;

    cp_q128(sb + A_QH, qhg, tid);
    {
        const uint32_t st = sb + A_ST;
        cp_kv64(st,        khg, tid);
        cp_v64 (st + 8192, vhg, 0, tid);
        asm volatile("cp.async.commit_group;" ::: "memory");
    }
    {
        const uint32_t st = sb + A_ST + A_STAGEB;
        cp_kv64(st,        khg + 64 * HDIM, tid);
        cp_v64 (st + 8192, vhg, 64, tid);
        asm volatile("cp.async.commit_group;" ::: "memory");
    }

    float ls0 = 0.f, ls1 = 0.f;
    float oacc[8][4];
#pragma unroll
    for (int i = 0; i < 8; i++)
#pragma unroll
        for (int j = 0; j < 4; j++) oacc[i][j] = 0.f;

    uint32_t qfh[4][4];
    const int brow = (lane & 7) + ((lane >> 4) << 3);
    const int bkh  = ((lane >> 3) & 1) * 16;
    const int NJ = SEQ / 64;   // 16
    int aph[2] = {0, 0};

    for (int j = 0; j < NJ; j++) {
        if (j < NJ - 1) asm volatile("cp.async.wait_group 1;" ::: "memory");
        else            asm volatile("cp.async.wait_group 0;" ::: "memory");
        __syncthreads();

        if (j == 0) {
            const int a_row = wid * 16 + (lane & 15);
            const int a_kh  = (lane >> 4) * 16;
#pragma unroll
            for (int ks = 0; ks < 4; ks++) {
                uint32_t off = (uint32_t)(a_row * 128 + ks * 32 + a_kh);
                LDSM_X4(qfh[ks][0], qfh[ks][1], qfh[ks][2], qfh[ks][3],
                        sb + A_QH + SWZ(off));
            }
        }

        const uint32_t st  = sb + A_ST + (j & 1) * A_STAGEB;
        const uint32_t sKH = st;
        const uint32_t sVH = st + 8192;

        // ---- S = Qh @ Kh^T (scale folded into Q; exp2 domain) ----
        float sacc[8][4];
#pragma unroll
        for (int i = 0; i < 8; i++)
#pragma unroll
            for (int k = 0; k < 4; k++) sacc[i][k] = 0.f;

#pragma unroll
        for (int ks = 0; ks < 4; ks++) {
#pragma unroll
            for (int nfp = 0; nfp < 4; nfp++) {
                uint32_t kh[4];
                uint32_t off = (uint32_t)((nfp * 16 + brow) * 128 + ks * 32 + bkh);
                LDSM_X4(kh[0], kh[1], kh[2], kh[3], sKH + SWZ(off));
                mma16816(sacc[2 * nfp],     qfh[ks], kh);
                mma16816(sacc[2 * nfp + 1], qfh[ks], kh + 2);
            }
        }

        // ---- static-shift softmax: p = exp2(s); per-thread l partials ----
#pragma unroll
        for (int nf = 0; nf < 8; nf++) {
            float e0 = ex2(sacc[nf][0]); sacc[nf][0] = e0;
            float e1 = ex2(sacc[nf][1]); sacc[nf][1] = e1;
            float e2 = ex2(sacc[nf][2]); sacc[nf][2] = e2;
            float e3 = ex2(sacc[nf][3]); sacc[nf][3] = e3;
            ls0 += e0 + e1;
            ls1 += e2 + e3;
        }

        // ---- O += P @ Vh  (P fragments straight from sacc) ----
#pragma unroll
        for (int ks = 0; ks < 4; ks++) {
            uint32_t ah[4];
            ah[0] = packh2(__float2half(sacc[2 * ks][0]),     __float2half(sacc[2 * ks][1]));
            ah[1] = packh2(__float2half(sacc[2 * ks][2]),     __float2half(sacc[2 * ks][3]));
            ah[2] = packh2(__float2half(sacc[2 * ks + 1][0]), __float2half(sacc[2 * ks + 1][1]));
            ah[3] = packh2(__float2half(sacc[2 * ks + 1][2]), __float2half(sacc[2 * ks + 1][3]));
#pragma unroll
            for (int nfp = 0; nfp < 4; nfp++) {
                uint32_t vh[4];
                uint32_t off = (uint32_t)((nfp * 16 + brow) * 128 + ks * 32 + bkh);
                LDSM_X4(vh[0], vh[1], vh[2], vh[3], sVH + SWZ(off));
                if (ks == 3 && nfp == 3)
                    MBAR_ARRIVE(sb + A_MBAR + (j & 1) * 8);
                mma16816(oacc[2 * nfp],     ah, vh);
                mma16816(oacc[2 * nfp + 1], ah, vh + 2);
            }
        }

        if (j + 2 < NJ) {
            MBAR_WAIT(sb + A_MBAR + (j & 1) * 8, aph[j & 1]);
            aph[j & 1] ^= 1;
            const uint32_t stn = sb + A_ST + (j & 1) * A_STAGEB;
            const int j0 = (j + 2) * 64;
            cp_kv64(stn,        khg + (size_t)j0 * HDIM, tid);
            cp_v64 (stn + 8192, vhg, j0, tid);
            asm volatile("cp.async.commit_group;" ::: "memory");
        }
    }

    // ---- final l reduction (once) + epilogue ----
    ls0 += __shfl_xor_sync(0xffffffff, ls0, 1);
    ls0 += __shfl_xor_sync(0xffffffff, ls0, 2);
    ls1 += __shfl_xor_sync(0xffffffff, ls1, 1);
    ls1 += __shfl_xor_sync(0xffffffff, ls1, 2);

    const int h = bh % NHEADS;
    const int b = bh / NHEADS;
    const int n0 = qt * 128 + wid * 16 + (lane >> 2);
    const float li0 = 1.f / ls0, li1 = 1.f / ls1;
#pragma unroll
    for (int onf = 0; onf < 8; onf++) {
        const int d = onf * 8 + (lane & 3) * 2;
        const size_t base0 = ((size_t)(b * SEQ + n0)) * DIM + h * HDIM + d;
        const size_t base1 = base0 + (size_t)8 * DIM;
        *(uint32_t*)(g_ah + base0) = packh2(__float2half(oacc[onf][0] * li0),
                                            __float2half(oacc[onf][1] * li0));
        *(uint32_t*)(g_ah + base1) = packh2(__float2half(oacc[onf][2] * li1),
                                            __float2half(oacc[onf][3] * li1));
    }
}

// ---------------------------------------------------------------------------
extern "C" void kernel_launch(void* const* d_in, const int* in_sizes, int n_in,
                              void* d_out, int out_size)
{
    (void)in_sizes; (void)n_in; (void)out_size;
    const float* x      = (const float*)d_in[0];
    const float* w_qkv  = (const float*)d_in[1];
    const float* w_proj = (const float*)d_in[2];
    const float* b_proj = (const float*)d_in[3];
    float* out = (float*)d_out;

    cudaFuncSetAttribute(qkv_gemm_kernel, cudaFuncAttributeMaxDynamicSharedMemorySize,
                         GEMM_SMEM);
    cudaFuncSetAttribute(proj_gemm_kernel, cudaFuncAttributeMaxDynamicSharedMemorySize,
                         PROJ_SMEM);
    cudaFuncSetAttribute(attn_hmma_kernel, cudaFuncAttributeMaxDynamicSharedMemorySize,
                         A_SMEM);

    __half *xh, *wqh, *wph, *ah;
    cudaGetSymbolAddress((void**)&xh,  g_xh);
    cudaGetSymbolAddress((void**)&wqh, g_wqh);
    cudaGetSymbolAddress((void**)&wph, g_wph);
    cudaGetSymbolAddress((void**)&ah,  g_ah);

    // 1. fp32 -> fp16 casts (x, w_qkv, w_proj)
    split_all_kernel<<<(SPLIT_Q3 + 255) / 256, 256>>>(x, w_qkv, w_proj);

    // 2. QKV GEMM (fp16, fp32 accum, CTA 128x128, 2 CTA/SM) -> q/k/v
    qkv_gemm_kernel<<<dim3(QKVN / 128, MTOT / 128), 256, GEMM_SMEM>>>(xh, wqh);

    // 3. fp16 flash attention (static-shift softmax, q-tile 128, 2 CTA/SM)
    attn_hmma_kernel<<<dim3(BATCH * NHEADS, SEQ / 128), 256, A_SMEM>>>();

    // 4. output projection (fp16, CTA 128x96 for wave shaping) -> out
    proj_gemm_kernel<<<dim3(DIM / 96, MTOT / 128), 256, PROJ_SMEM>>>(
        ah, wph, b_proj, out);
}

// round 17
// speedup vs baseline: 1.0113x; 1.0113x over previous
#include <cuda_runtime.h>
#include <cuda_fp16.h>
#include <cstdint>

#define DIM     768
#define NHEADS  12
#define HDIM    64
#define BATCH   8
#define SEQ     1024
#define MTOT    (BATCH * SEQ)      // 8192
#define QKVN    (3 * DIM)          // 2304
// Q pre-scale: 1/sqrt(64) * log2(e)  (softmax done in exp2 domain, no shift)
#define QK_SCALE (0.125f * 1.4426950408889634f)

// ---------------------------------------------------------------------------
// Scratch (__device__ globals; no allocations allowed)
// ---------------------------------------------------------------------------
__device__ __half g_qh[BATCH * NHEADS * SEQ * HDIM];
__device__ __half g_kh[BATCH * NHEADS * SEQ * HDIM];
__device__ __half g_vh[BATCH * NHEADS * HDIM * SEQ];     // [B,H,D,N]
__device__ __half g_xh[MTOT * DIM];
__device__ __half g_wqh[QKVN * DIM];
__device__ __half g_wph[DIM * DIM];
__device__ __half g_ah[MTOT * DIM];

__device__ __forceinline__ uint32_t smem_u32(const void* p) {
    uint32_t a;
    asm("{ .reg .u64 t; cvta.to.shared.u64 t, %1; cvt.u32.u64 %0, t; }"
        : "=r"(a) : "l"(p));
    return a;
}

#define SWZ(off) ((off) ^ (((off) >> 3) & 0x70))

#define LDSM_X4(r0, r1, r2, r3, addr) \
    asm volatile("ldmatrix.sync.aligned.m8n8.x4.shared.b16 {%0,%1,%2,%3}, [%4];" \
        : "=r"(r0), "=r"(r1), "=r"(r2), "=r"(r3) : "r"(addr))

#define MBAR_INIT(addr, cnt) \
    asm volatile("mbarrier.init.shared.b64 [%0], %1;" \
        :: "r"((uint32_t)(addr)), "r"((uint32_t)(cnt)) : "memory")
#define MBAR_ARRIVE(addr) \
    asm volatile("mbarrier.arrive.shared.b64 _, [%0];" \
        :: "r"((uint32_t)(addr)) : "memory")
#define MBAR_WAIT(mbar_smem_addr, phase_parity) do { \
    uint32_t _mbar = (uint32_t)(mbar_smem_addr); \
    uint32_t _parity = (uint32_t)(phase_parity); \
    uint32_t _done; \
    asm volatile("{\n\t.reg .pred p;\n\t" \
        "mbarrier.try_wait.parity.acquire.cta.shared::cta.b64 p, [%1], %2;\n\t" \
        "selp.b32 %0, 1, 0, p;\n\t}" \
        : "=r"(_done) : "r"(_mbar), "r"(_parity) : "memory"); \
    if (!_done) { \
        asm volatile("{\n\t.reg .pred P1;\n\t" \
            "WAIT_LOOP_%=:\n\t" \
            "mbarrier.try_wait.parity.acquire.cta.shared::cta.b64 P1, [%0], %1, 0x989680;\n\t" \
            "@P1 bra.uni WAIT_DONE_%=;\n\t" \
            "bra.uni WAIT_LOOP_%=;\n\t" \
            "WAIT_DONE_%=:\n\t}" \
            :: "r"(_mbar), "r"(_parity) : "memory"); \
    } \
} while (0)

__device__ __forceinline__ void mma16816(float* c, const uint32_t* a,
                                         const uint32_t* b)
{
    asm volatile("mma.sync.aligned.m16n8k16.row.col.f32.f16.f16.f32 "
        "{%0,%1,%2,%3}, {%4,%5,%6,%7}, {%8,%9}, {%0,%1,%2,%3};"
        : "+f"(c[0]), "+f"(c[1]), "+f"(c[2]), "+f"(c[3])
        : "r"(a[0]), "r"(a[1]), "r"(a[2]), "r"(a[3]), "r"(b[0]), "r"(b[1]));
}

__device__ __forceinline__ uint32_t packh2(__half x, __half y) {
    __half2 t = __half2(x, y);
    return *(uint32_t*)&t;
}
__device__ __forceinline__ float ex2(float x) {
    float y;
    asm("ex2.approx.ftz.f32 %0, %1;" : "=f"(y) : "f"(x));
    return y;
}

// ---------------------------------------------------------------------------
// Fused conversion: fp32 -> fp16 casts; 2 float4 per thread (issue-optimized)
// ---------------------------------------------------------------------------
#define SPLIT_Q1 (MTOT * DIM / 4)
#define SPLIT_Q2 (SPLIT_Q1 + QKVN * DIM / 4)
#define SPLIT_Q3 (SPLIT_Q2 + DIM * DIM / 4)
#define SPLIT_T  ((SPLIT_Q3 + 1) / 2)

__global__ __launch_bounds__(256)
void split_all_kernel(const float* __restrict__ x, const float* __restrict__ wq,
                      const float* __restrict__ wp)
{
    const int t = blockIdx.x * blockDim.x + threadIdx.x;
#pragma unroll
    for (int u = 0; u < 2; u++) {
        const int i = t * 2 + u;
        if (i >= SPLIT_Q3) return;
        const float* src;
        __half* dst;
        int off;
        if (i < SPLIT_Q1)      { src = x;  dst = g_xh;  off = i; }
        else if (i < SPLIT_Q2) { src = wq; dst = g_wqh; off = i - SPLIT_Q1; }
        else                   { src = wp; dst = g_wph; off = i - SPLIT_Q2; }

        float4 v = ((const float4*)src)[off];
        __half2* hp = (__half2*)(dst + off * 4);
        hp[0] = __half2(__float2half(v.x), __float2half(v.y));
        hp[1] = __half2(__float2half(v.z), __float2half(v.w));
    }
}

// ---------------------------------------------------------------------------
// Plain-fp16 HMMA GEMM core config (converged optimum): CTA 128x128,
// 8 warps (2m x 4n), warp tile 64x32, KC=64, 2-stage cp.async,
// 64KB smem -> 2 CTAs/SM.
// ---------------------------------------------------------------------------
#define KC        64
#define NKC       (DIM / KC)                 // 12
#define G_AH      0
#define G_BH      16384
#define G_STAGE   32768
#define G_MBAR    (2 * G_STAGE)
#define GEMM_SMEM (2 * G_STAGE + 64)

__device__ __forceinline__ void cp_tile128(uint32_t dst, const __half* g, int tid)
{
#pragma unroll
    for (int i = 0; i < 4; i++) {
        const int p = tid + i * 256;
        const int r = p >> 3;
        const int c = p & 7;
        const uint32_t off = (uint32_t)(r * 128 + c * 16);
        const void* src = (const char*)(g + (size_t)r * DIM) + c * 16;
        asm volatile("cp.async.cg.shared.global [%0], [%1], 16;"
                     :: "r"(dst + SWZ(off)), "l"(src) : "memory");
    }
}

// ---- QKV GEMM: scatter q/k/v fp16 (Q pre-scaled, V transposed direct) ----
__global__ __launch_bounds__(256, 2)
void qkv_gemm_kernel(const __half* __restrict__ Ah, const __half* __restrict__ Bh)
{
    extern __shared__ char smem[];
    const uint32_t sbase = smem_u32(smem);
    const int tid  = threadIdx.x;
    const int wid  = tid >> 5;
    const int lane = tid & 31;
    const int wm   = wid >> 2;
    const int wn   = wid & 3;
    const int n0   = blockIdx.x * 128;
    const int m0   = blockIdx.y * 128;

    if (tid == 0) {
        MBAR_INIT(sbase + G_MBAR, 256);
        MBAR_INIT(sbase + G_MBAR + 8, 256);
    }

    const __half* Ah0 = Ah + (size_t)m0 * DIM;
    const __half* Bh0 = Bh + (size_t)n0 * DIM;

    float acc[4][4][4];
#pragma unroll
    for (int i = 0; i < 4; i++)
#pragma unroll
        for (int j = 0; j < 4; j++)
#pragma unroll
            for (int k = 0; k < 4; k++) acc[i][j][k] = 0.f;

    {
        cp_tile128(sbase + G_AH, Ah0, tid);
        cp_tile128(sbase + G_BH, Bh0, tid);
        asm volatile("cp.async.commit_group;" ::: "memory");
    }

    const int a_row = wm * 64 + (lane & 15);
    const int a_kh  = (lane >> 4) * 16;
    const int b_row = wn * 32 + (lane & 7) + ((lane >> 4) << 3);
    const int b_kh  = ((lane >> 3) & 1) * 16;

    int ph[2] = {0, 0};

    for (int kc = 0; kc < NKC; kc++) {
        if (kc + 1 < NKC) {
            const int t = (kc + 1) & 1;
            if (kc >= 1) {
                MBAR_WAIT(sbase + G_MBAR + t * 8, ph[t]);
                ph[t] ^= 1;
            }
            const uint32_t st = sbase + t * G_STAGE;
            const int koff = (kc + 1) * KC;
            cp_tile128(st + G_AH, Ah0 + koff, tid);
            cp_tile128(st + G_BH, Bh0 + koff, tid);
            asm volatile("cp.async.commit_group;" ::: "memory");
            asm volatile("cp.async.wait_group 1;" ::: "memory");
        } else {
            asm volatile("cp.async.wait_group 0;" ::: "memory");
        }
        __syncthreads();

        const uint32_t st = sbase + (kc & 1) * G_STAGE;
        const uint32_t sAh = st + G_AH;
        const uint32_t sBh = st + G_BH;

#pragma unroll
        for (int ks = 0; ks < KC / 16; ks++) {
            uint32_t ah[4][4], bh[2][4];
#pragma unroll
            for (int mf = 0; mf < 4; mf++) {
                uint32_t off = (uint32_t)((a_row + mf * 16) * 128 + ks * 32 + a_kh);
                LDSM_X4(ah[mf][0], ah[mf][1], ah[mf][2], ah[mf][3], sAh + SWZ(off));
            }
#pragma unroll
            for (int nfp = 0; nfp < 2; nfp++) {
                uint32_t off = (uint32_t)((b_row + nfp * 16) * 128 + ks * 32 + b_kh);
                LDSM_X4(bh[nfp][0], bh[nfp][1], bh[nfp][2], bh[nfp][3], sBh + SWZ(off));
            }
            if (ks == KC / 16 - 1)
                MBAR_ARRIVE(sbase + G_MBAR + (kc & 1) * 8);
#pragma unroll
            for (int mf = 0; mf < 4; mf++)
#pragma unroll
                for (int nf = 0; nf < 4; nf++)
                    mma16816(acc[mf][nf], ah[mf], &bh[nf >> 1][(nf & 1) * 2]);
        }
    }

    const int rbase = m0 + wm * 64 + (lane >> 2);
    const int cbase = n0 + wn * 32 + (lane & 3) * 2;
    const int sel = n0 / DIM;

#pragma unroll
    for (int nf = 0; nf < 4; nf++) {
        const int gc = cbase + nf * 8;
        const int h  = (gc % DIM) >> 6;
        const int d  = gc & 63;
#pragma unroll
        for (int mf = 0; mf < 4; mf++) {
#pragma unroll
            for (int rr = 0; rr < 2; rr++) {
                const int m = rbase + mf * 16 + rr * 8;
                const int b = m >> 10;
                const int n = m & 1023;
                float v0 = acc[mf][nf][rr * 2];
                float v1 = acc[mf][nf][rr * 2 + 1];
                if (sel == 0) {
                    v0 *= QK_SCALE; v1 *= QK_SCALE;
                    const size_t a = ((size_t)((b * NHEADS + h) * SEQ + n)) * HDIM + d;
                    *(__half2*)(g_qh + a) = __half2(__float2half(v0), __float2half(v1));
                } else if (sel == 1) {
                    const size_t a = ((size_t)((b * NHEADS + h) * SEQ + n)) * HDIM + d;
                    *(__half2*)(g_kh + a) = __half2(__float2half(v0), __float2half(v1));
                } else {
                    const size_t a = ((size_t)((b * NHEADS + h) * HDIM + d)) * SEQ + n;
                    g_vh[a]       = __float2half(v0);
                    g_vh[a + SEQ] = __float2half(v1);
                }
            }
        }
    }
}

// ---- Proj GEMM: same 128x128 config, OUT = Ah @ Wh^T + bias ----
__global__ __launch_bounds__(256, 2)
void proj_gemm_kernel(const __half* __restrict__ Ah, const __half* __restrict__ Bh,
                      const float* __restrict__ bias, float* __restrict__ OUT)
{
    extern __shared__ char smem[];
    const uint32_t sbase = smem_u32(smem);
    const int tid  = threadIdx.x;
    const int wid  = tid >> 5;
    const int lane = tid & 31;
    const int wm   = wid >> 2;
    const int wn   = wid & 3;
    const int n0   = blockIdx.x * 128;
    const int m0   = blockIdx.y * 128;

    if (tid == 0) {
        MBAR_INIT(sbase + G_MBAR, 256);
        MBAR_INIT(sbase + G_MBAR + 8, 256);
    }

    const __half* Ah0 = Ah + (size_t)m0 * DIM;
    const __half* Bh0 = Bh + (size_t)n0 * DIM;

    float acc[4][4][4];
#pragma unroll
    for (int i = 0; i < 4; i++)
#pragma unroll
        for (int j = 0; j < 4; j++)
#pragma unroll
            for (int k = 0; k < 4; k++) acc[i][j][k] = 0.f;

    {
        cp_tile128(sbase + G_AH, Ah0, tid);
        cp_tile128(sbase + G_BH, Bh0, tid);
        asm volatile("cp.async.commit_group;" ::: "memory");
    }

    const int a_row = wm * 64 + (lane & 15);
    const int a_kh  = (lane >> 4) * 16;
    const int b_row = wn * 32 + (lane & 7) + ((lane >> 4) << 3);
    const int b_kh  = ((lane >> 3) & 1) * 16;

    int ph[2] = {0, 0};

    for (int kc = 0; kc < NKC; kc++) {
        if (kc + 1 < NKC) {
            const int t = (kc + 1) & 1;
            if (kc >= 1) {
                MBAR_WAIT(sbase + G_MBAR + t * 8, ph[t]);
                ph[t] ^= 1;
            }
            const uint32_t st = sbase + t * G_STAGE;
            const int koff = (kc + 1) * KC;
            cp_tile128(st + G_AH, Ah0 + koff, tid);
            cp_tile128(st + G_BH, Bh0 + koff, tid);
            asm volatile("cp.async.commit_group;" ::: "memory");
            asm volatile("cp.async.wait_group 1;" ::: "memory");
        } else {
            asm volatile("cp.async.wait_group 0;" ::: "memory");
        }
        __syncthreads();

        const uint32_t st = sbase + (kc & 1) * G_STAGE;
        const uint32_t sAh = st + G_AH;
        const uint32_t sBh = st + G_BH;

#pragma unroll
        for (int ks = 0; ks < KC / 16; ks++) {
            uint32_t ah[4][4], bh[2][4];
#pragma unroll
            for (int mf = 0; mf < 4; mf++) {
                uint32_t off = (uint32_t)((a_row + mf * 16) * 128 + ks * 32 + a_kh);
                LDSM_X4(ah[mf][0], ah[mf][1], ah[mf][2], ah[mf][3], sAh + SWZ(off));
            }
#pragma unroll
            for (int nfp = 0; nfp < 2; nfp++) {
                uint32_t off = (uint32_t)((b_row + nfp * 16) * 128 + ks * 32 + b_kh);
                LDSM_X4(bh[nfp][0], bh[nfp][1], bh[nfp][2], bh[nfp][3], sBh + SWZ(off));
            }
            if (ks == KC / 16 - 1)
                MBAR_ARRIVE(sbase + G_MBAR + (kc & 1) * 8);
#pragma unroll
            for (int mf = 0; mf < 4; mf++)
#pragma unroll
                for (int nf = 0; nf < 4; nf++)
                    mma16816(acc[mf][nf], ah[mf], &bh[nf >> 1][(nf & 1) * 2]);
        }
    }

    const int rbase = m0 + wm * 64 + (lane >> 2);
    const int cbase = n0 + wn * 32 + (lane & 3) * 2;

#pragma unroll
    for (int nf = 0; nf < 4; nf++) {
        const int gc = cbase + nf * 8;
        const float2 bv = *(const float2*)(bias + gc);
#pragma unroll
        for (int mf = 0; mf < 4; mf++) {
#pragma unroll
            for (int rr = 0; rr < 2; rr++) {
                const int m = rbase + mf * 16 + rr * 8;
                float* p = OUT + (size_t)m * DIM + gc;
                *(float2*)p = make_float2(acc[mf][nf][rr * 2] + bv.x,
                                          acc[mf][nf][rr * 2 + 1] + bv.y);
            }
        }
    }
}

// ---------------------------------------------------------------------------
// fp16 flash attention (measured best): q-tile 128, 2 CTAs/SM,
// static-shift softmax. KV j-tile 64, 2-stage cp.async; 48KB smem.
// ---------------------------------------------------------------------------
#define A_QH     0                 // 128 x 64h = 16KB
#define A_ST     16384             // stage: KH 0, VH 8192
#define A_STAGEB 16384
#define A_MBAR   (A_ST + 2 * A_STAGEB)
#define A_SMEM   (A_MBAR + 64)

__device__ __forceinline__ void cp_kv64(uint32_t dst, const __half* g, int tid)
{
#pragma unroll
    for (int i = 0; i < 2; i++) {
        const int p = tid + i * 256;
        const int r = p >> 3;
        const int c = p & 7;
        const uint32_t off = (uint32_t)(r * 128 + c * 16);
        const void* src = (const char*)(g + (size_t)r * 64) + c * 16;
        asm volatile("cp.async.cg.shared.global [%0], [%1], 16;"
                     :: "r"(dst + SWZ(off)), "l"(src) : "memory");
    }
}
__device__ __forceinline__ void cp_q128(uint32_t dst, const __half* g, int tid)
{
#pragma unroll
    for (int i = 0; i < 4; i++) {
        const int p = tid + i * 256;
        const int r = p >> 3;
        const int c = p & 7;
        const uint32_t off = (uint32_t)(r * 128 + c * 16);
        const void* src = (const char*)(g + (size_t)r * 64) + c * 16;
        asm volatile("cp.async.cg.shared.global [%0], [%1], 16;"
                     :: "r"(dst + SWZ(off)), "l"(src) : "memory");
    }
}
__device__ __forceinline__ void cp_v64(uint32_t dst, const __half* g, int j0, int tid)
{
#pragma unroll
    for (int i = 0; i < 2; i++) {
        const int p = tid + i * 256;
        const int d = p >> 3;
        const int c = p & 7;
        const void* src = g + (size_t)d * SEQ + j0 + c * 8;
        const uint32_t off = (uint32_t)(d * 128 + c * 16);
        asm volatile("cp.async.cg.shared.global [%0], [%1], 16;"
                     :: "r"(dst + SWZ(off)), "l"(src) : "memory");
    }
}

__global__ __launch_bounds__(256, 2)
void attn_hmma_kernel()
{
    extern __shared__ char smem[];
    const uint32_t sb = smem_u32(smem);
    const int tid = threadIdx.x, wid = tid >> 5, lane = tid & 31;
    const int bh = blockIdx.x, qt = blockIdx.y;

    if (tid == 0) {
        MBAR_INIT(sb + A_MBAR, 256);
        MBAR_INIT(sb + A_MBAR + 8, 256);
    }

    const __half* qhg = g_qh + ((size_t)bh * SEQ + qt * 128) * HDIM;
    const __half* khg = g_kh + (size_t)bh * SEQ * HDIM;
    const __half* vhg = g_vh + (size_t)bh * HDIM * SEQ;

    cp_q128(sb + A_QH, qhg, tid);
    {
        const uint32_t st = sb + A_ST;
        cp_kv64(st,        khg, tid);
        cp_v64 (st + 8192, vhg, 0, tid);
        asm volatile("cp.async.commit_group;" ::: "memory");
    }
    {
        const uint32_t st = sb + A_ST + A_STAGEB;
        cp_kv64(st,        khg + 64 * HDIM, tid);
        cp_v64 (st + 8192, vhg, 64, tid);
        asm volatile("cp.async.commit_group;" ::: "memory");
    }

    float ls0 = 0.f, ls1 = 0.f;
    float oacc[8][4];
#pragma unroll
    for (int i = 0; i < 8; i++)
#pragma unroll
        for (int j = 0; j < 4; j++) oacc[i][j] = 0.f;

    uint32_t qfh[4][4];
    const int brow = (lane & 7) + ((lane >> 4) << 3);
    const int bkh  = ((lane >> 3) & 1) * 16;
    const int NJ = SEQ / 64;   // 16
    int aph[2] = {0, 0};

    for (int j = 0; j < NJ; j++) {
        if (j < NJ - 1) asm volatile("cp.async.wait_group 1;" ::: "memory");
        else            asm volatile("cp.async.wait_group 0;" ::: "memory");
        __syncthreads();

        if (j == 0) {
            const int a_row = wid * 16 + (lane & 15);
            const int a_kh  = (lane >> 4) * 16;
#pragma unroll
            for (int ks = 0; ks < 4; ks++) {
                uint32_t off = (uint32_t)(a_row * 128 + ks * 32 + a_kh);
                LDSM_X4(qfh[ks][0], qfh[ks][1], qfh[ks][2], qfh[ks][3],
                        sb + A_QH + SWZ(off));
            }
        }

        const uint32_t st  = sb + A_ST + (j & 1) * A_STAGEB;
        const uint32_t sKH = st;
        const uint32_t sVH = st + 8192;

        // ---- S = Qh @ Kh^T (scale folded into Q; exp2 domain) ----
        float sacc[8][4];
#pragma unroll
        for (int i = 0; i < 8; i++)
#pragma unroll
            for (int k = 0; k < 4; k++) sacc[i][k] = 0.f;

#pragma unroll
        for (int ks = 0; ks < 4; ks++) {
#pragma unroll
            for (int nfp = 0; nfp < 4; nfp++) {
                uint32_t kh[4];
                uint32_t off = (uint32_t)((nfp * 16 + brow) * 128 + ks * 32 + bkh);
                LDSM_X4(kh[0], kh[1], kh[2], kh[3], sKH + SWZ(off));
                mma16816(sacc[2 * nfp],     qfh[ks], kh);
                mma16816(sacc[2 * nfp + 1], qfh[ks], kh + 2);
            }
        }

        // ---- static-shift softmax: p = exp2(s); per-thread l partials ----
#pragma unroll
        for (int nf = 0; nf < 8; nf++) {
            float e0 = ex2(sacc[nf][0]); sacc[nf][0] = e0;
            float e1 = ex2(sacc[nf][1]); sacc[nf][1] = e1;
            float e2 = ex2(sacc[nf][2]); sacc[nf][2] = e2;
            float e3 = ex2(sacc[nf][3]); sacc[nf][3] = e3;
            ls0 += e0 + e1;
            ls1 += e2 + e3;
        }

        // ---- O += P @ Vh  (P fragments straight from sacc) ----
#pragma unroll
        for (int ks = 0; ks < 4; ks++) {
            uint32_t ah[4];
            ah[0] = packh2(__float2half(sacc[2 * ks][0]),     __float2half(sacc[2 * ks][1]));
            ah[1] = packh2(__float2half(sacc[2 * ks][2]),     __float2half(sacc[2 * ks][3]));
            ah[2] = packh2(__float2half(sacc[2 * ks + 1][0]), __float2half(sacc[2 * ks + 1][1]));
            ah[3] = packh2(__float2half(sacc[2 * ks + 1][2]), __float2half(sacc[2 * ks + 1][3]));
#pragma unroll
            for (int nfp = 0; nfp < 4; nfp++) {
                uint32_t vh[4];
                uint32_t off = (uint32_t)((nfp * 16 + brow) * 128 + ks * 32 + bkh);
                LDSM_X4(vh[0], vh[1], vh[2], vh[3], sVH + SWZ(off));
                if (ks == 3 && nfp == 3)
                    MBAR_ARRIVE(sb + A_MBAR + (j & 1) * 8);
                mma16816(oacc[2 * nfp],     ah, vh);
                mma16816(oacc[2 * nfp + 1], ah, vh + 2);
            }
        }

        if (j + 2 < NJ) {
            MBAR_WAIT(sb + A_MBAR + (j & 1) * 8, aph[j & 1]);
            aph[j & 1] ^= 1;
            const uint32_t stn = sb + A_ST + (j & 1) * A_STAGEB;
            const int j0 = (j + 2) * 64;
            cp_kv64(stn,        khg + (size_t)j0 * HDIM, tid);
            cp_v64 (stn + 8192, vhg, j0, tid);
            asm volatile("cp.async.commit_group;" ::: "memory");
        }
    }

    // ---- final l reduction (once) + epilogue ----
    ls0 += __shfl_xor_sync(0xffffffff, ls0, 1);
    ls0 += __shfl_xor_sync(0xffffffff, ls0, 2);
    ls1 += __shfl_xor_sync(0xffffffff, ls1, 1);
    ls1 += __shfl_xor_sync(0xffffffff, ls1, 2);

    const int h = bh % NHEADS;
    const int b = bh / NHEADS;
    const int n0 = qt * 128 + wid * 16 + (lane >> 2);
    const float li0 = 1.f / ls0, li1 = 1.f / ls1;
#pragma unroll
    for (int onf = 0; onf < 8; onf++) {
        const int d = onf * 8 + (lane & 3) * 2;
        const size_t base0 = ((size_t)(b * SEQ + n0)) * DIM + h * HDIM + d;
        const size_t base1 = base0 + (size_t)8 * DIM;
        *(uint32_t*)(g_ah + base0) = packh2(__float2half(oacc[onf][0] * li0),
                                            __float2half(oacc[onf][1] * li0));
        *(uint32_t*)(g_ah + base1) = packh2(__float2half(oacc[onf][2] * li1),
                                            __float2half(oacc[onf][3] * li1));
    }
}

// ---------------------------------------------------------------------------
extern "C" void kernel_launch(void* const* d_in, const int* in_sizes, int n_in,
                              void* d_out, int out_size)
{
    (void)in_sizes; (void)n_in; (void)out_size;
    const float* x      = (const float*)d_in[0];
    const float* w_qkv  = (const float*)d_in[1];
    const float* w_proj = (const float*)d_in[2];
    const float* b_proj = (const float*)d_in[3];
    float* out = (float*)d_out;

    cudaFuncSetAttribute(qkv_gemm_kernel, cudaFuncAttributeMaxDynamicSharedMemorySize,
                         GEMM_SMEM);
    cudaFuncSetAttribute(proj_gemm_kernel, cudaFuncAttributeMaxDynamicSharedMemorySize,
                         GEMM_SMEM);
    cudaFuncSetAttribute(attn_hmma_kernel, cudaFuncAttributeMaxDynamicSharedMemorySize,
                         A_SMEM);

    __half *xh, *wqh, *wph, *ah;
    cudaGetSymbolAddress((void**)&xh,  g_xh);
    cudaGetSymbolAddress((void**)&wqh, g_wqh);
    cudaGetSymbolAddress((void**)&wph, g_wph);
    cudaGetSymbolAddress((void**)&ah,  g_ah);

    // 1. fp32 -> fp16 casts (x, w_qkv, w_proj), 2 float4 per thread
    split_all_kernel<<<(SPLIT_T + 255) / 256, 256>>>(x, w_qkv, w_proj);

    // 2. QKV GEMM (fp16, fp32 accum, CTA 128x128, 2 CTA/SM) -> q/k/v
    qkv_gemm_kernel<<<dim3(QKVN / 128, MTOT / 128), 256, GEMM_SMEM>>>(xh, wqh);

    // 3. fp16 flash attention (static-shift softmax, q-tile 128, 2 CTA/SM)
    attn_hmma_kernel<<<dim3(BATCH * NHEADS, SEQ / 128), 256, A_SMEM>>>();

    // 4. output projection (fp16, fp32 accum, CTA 128x128, 2 CTA/SM) -> out
    proj_gemm_kernel<<<dim3(DIM / 128, MTOT / 128), 256, GEMM_SMEM>>>(
        ah, wph, b_proj, out);
}